// round 8
// baseline (speedup 1.0000x reference)
#include <cuda_runtime.h>
#include <math.h>
#include <stdint.h>

#define BATCH 8
#define NPTS 2048
#define ROWS_PB 32                 // rows of M per block
#define STAGES 4                   // smem ring depth (3 in flight)
#define GRIDX (NPTS / ROWS_PB)     // 64 blocks per batch

__device__ float g_part[BATCH][GRIDX][12];
__device__ unsigned int g_count[BATCH];   // zero-init; reset each call

__device__ __forceinline__ void cp_async16(uint32_t dst, const float* src) {
    asm volatile("cp.async.cg.shared.global [%0], [%1], 16;\n"
                 :: "r"(dst), "l"(src));
}
__device__ __forceinline__ void cp_commit() {
    asm volatile("cp.async.commit_group;\n" ::: "memory");
}
template <int N>
__device__ __forceinline__ void cp_wait() {
    asm volatile("cp.async.wait_group %0;\n" :: "n"(N) : "memory");
}

// ---------------------------------------------------------------------------
// grid = (GRIDX, BATCH), block = 256. Thread t owns columns 8t..8t+7 of every
// row. Per stage (= one 8KB row of M) each thread cp.asyncs its own 32B into
// its own ring slot and consumes ONLY its own data -> no block barriers in the
// pipeline loop. Accumulates w[8][3] = sum_n M[n,m] q[n,:] and s[8] = sum_n
// M[n,m]; contracts with P once at the end. Last block per batch does means,
// S, polar, R, t.
// ---------------------------------------------------------------------------
__global__ void __launch_bounds__(256, 4) fused_kernel(
    const float* __restrict__ P,
    const float* __restrict__ Q,
    const float* __restrict__ M,
    float* __restrict__ out) {
    const int b = blockIdx.y;
    const int rowblk = blockIdx.x;
    const int tid = threadIdx.x;
    const int warp = tid >> 5;
    const int lane = tid & 31;

    __shared__ __align__(16) float ring[STAGES * NPTS];   // 32 KB
    __shared__ float sQ[ROWS_PB * 3];                     // q for this block's rows
    __shared__ float sacc[8][12];
    __shared__ float warpSums[8][6];
    __shared__ float sTv[12];
    __shared__ int sIsLast;

    const float* Pb = P + (size_t)b * NPTS * 3;
    const float* Qb = Q + (size_t)b * NPTS * 3;
    const float* Mb = M + (size_t)b * NPTS * NPTS + (size_t)rowblk * ROWS_PB * NPTS;

    const uint32_t sbase = (uint32_t)__cvta_generic_to_shared(ring);
    const float* gsrc = Mb + tid * 8;                 // thread's 32B within a row
    const uint32_t sdst = sbase + (uint32_t)(tid * 32);

    auto issue = [&](int it) {
        uint32_t so = (uint32_t)((it & (STAGES - 1)) * NPTS * 4);
        const float* g = gsrc + (size_t)it * NPTS;
        cp_async16(sdst + so, g);
        cp_async16(sdst + so + 16, g + 4);
    };

    // preload q for this block's 32 rows
    if (tid < ROWS_PB * 3) sQ[tid] = Qb[rowblk * ROWS_PB * 3 + tid];

    // prologue
    #pragma unroll
    for (int s = 0; s < STAGES - 1; s++) {
        issue(s);
        cp_commit();
    }
    __syncthreads();   // sQ visible (only barrier before the end)

    float w[8][3];
    float cs[8];
    #pragma unroll
    for (int k = 0; k < 8; k++) {
        w[k][0] = w[k][1] = w[k][2] = 0.f;
        cs[k] = 0.f;
    }

    const float4* myslot = reinterpret_cast<const float4*>(ring + tid * 8);

    #pragma unroll 4
    for (int it = 0; it < ROWS_PB; it++) {
        if (it + STAGES - 1 < ROWS_PB) issue(it + STAGES - 1);
        cp_commit();
        cp_wait<STAGES - 1>();

        float q0 = sQ[it * 3 + 0];
        float q1 = sQ[it * 3 + 1];
        float q2 = sQ[it * 3 + 2];

        const float4* sl = myslot + (size_t)(it & (STAGES - 1)) * (NPTS / 4);
        float4 a = sl[0];
        float4 c = sl[1];
        float m[8] = {a.x, a.y, a.z, a.w, c.x, c.y, c.z, c.w};

        #pragma unroll
        for (int k = 0; k < 8; k++) {
            w[k][0] += m[k] * q0;
            w[k][1] += m[k] * q1;
            w[k][2] += m[k] * q2;
            cs[k]   += m[k];
        }
    }

    // contract with P: T[i][j] = sum_k P[col_k][i] * w[k][j]; v[i] = sum_k P*s
    float T[9] = {0,0,0,0,0,0,0,0,0};
    float v[3] = {0,0,0};
    {
        const float* pp = Pb + (size_t)tid * 24;    // 8 cols * 3 comps
        #pragma unroll
        for (int k = 0; k < 8; k++) {
            float px = __ldg(pp + k * 3 + 0);
            float py = __ldg(pp + k * 3 + 1);
            float pz = __ldg(pp + k * 3 + 2);
            T[0] += px * w[k][0]; T[1] += px * w[k][1]; T[2] += px * w[k][2];
            T[3] += py * w[k][0]; T[4] += py * w[k][1]; T[5] += py * w[k][2];
            T[6] += pz * w[k][0]; T[7] += pz * w[k][1]; T[8] += pz * w[k][2];
            v[0] += px * cs[k];   v[1] += py * cs[k];   v[2] += pz * cs[k];
        }
    }

    // block reduce 12 values
    float r12[12] = {T[0],T[1],T[2],T[3],T[4],T[5],T[6],T[7],T[8],v[0],v[1],v[2]};
    #pragma unroll
    for (int off = 16; off > 0; off >>= 1) {
        #pragma unroll
        for (int j = 0; j < 12; j++)
            r12[j] += __shfl_xor_sync(0xffffffffu, r12[j], off);
    }
    if (lane == 0) {
        #pragma unroll
        for (int j = 0; j < 12; j++) sacc[warp][j] = r12[j];
    }
    __syncthreads();
    if (tid < 12) {
        float s = 0.f;
        #pragma unroll
        for (int wv = 0; wv < 8; wv++) s += sacc[wv][tid];
        g_part[b][rowblk][tid] = s;
    }
    __threadfence();
    __syncthreads();

    // ---------------- last block of this batch finishes ----------------
    if (tid == 0) {
        unsigned int old = atomicAdd(&g_count[b], 1u);
        sIsLast = (old == GRIDX - 1u) ? 1 : 0;
    }
    __syncthreads();
    if (!sIsLast) return;
    __threadfence();   // acquire: other blocks' g_part writes visible

    // --- means of P and Q via float4 triples from global ---
    float sp0 = 0.f, sp1 = 0.f, sp2 = 0.f;
    float sq0 = 0.f, sq1 = 0.f, sq2 = 0.f;
    const float4* P4 = reinterpret_cast<const float4*>(Pb);
    const float4* Q4 = reinterpret_cast<const float4*>(Qb);
    #pragma unroll
    for (int t = 0; t < 2; t++) {
        int tr = tid + t * 256;               // triple index, 512 total
        float4 A = P4[tr * 3 + 0];
        float4 Bv = P4[tr * 3 + 1];
        float4 C = P4[tr * 3 + 2];
        sp0 += A.x + A.w + Bv.z + C.y;
        sp1 += A.y + Bv.x + Bv.w + C.z;
        sp2 += A.z + Bv.y + C.x + C.w;
        float4 A2 = Q4[tr * 3 + 0];
        float4 B2 = Q4[tr * 3 + 1];
        float4 C2 = Q4[tr * 3 + 2];
        sq0 += A2.x + A2.w + B2.z + C2.y;
        sq1 += A2.y + B2.x + B2.w + C2.z;
        sq2 += A2.z + B2.y + C2.x + C2.w;
    }
    #pragma unroll
    for (int off = 16; off > 0; off >>= 1) {
        sp0 += __shfl_xor_sync(0xffffffffu, sp0, off);
        sp1 += __shfl_xor_sync(0xffffffffu, sp1, off);
        sp2 += __shfl_xor_sync(0xffffffffu, sp2, off);
        sq0 += __shfl_xor_sync(0xffffffffu, sq0, off);
        sq1 += __shfl_xor_sync(0xffffffffu, sq1, off);
        sq2 += __shfl_xor_sync(0xffffffffu, sq2, off);
    }
    if (lane == 0) {
        warpSums[warp][0] = sp0; warpSums[warp][1] = sp1; warpSums[warp][2] = sp2;
        warpSums[warp][3] = sq0; warpSums[warp][4] = sq1; warpSums[warp][5] = sq2;
    }

    // --- warp 0 reduces the GRIDX x 12 partials ---
    if (warp == 0) {
        float Tv[12];
        #pragma unroll
        for (int j = 0; j < 12; j++) Tv[j] = 0.f;
        #pragma unroll
        for (int r = 0; r < GRIDX / 32; r++) {
            const float* row = g_part[b][lane + r * 32];
            #pragma unroll
            for (int j = 0; j < 12; j++) Tv[j] += row[j];
        }
        #pragma unroll
        for (int off = 16; off > 0; off >>= 1) {
            #pragma unroll
            for (int j = 0; j < 12; j++)
                Tv[j] += __shfl_xor_sync(0xffffffffu, Tv[j], off);
        }
        if (lane == 0) {
            #pragma unroll
            for (int j = 0; j < 12; j++) sTv[j] = Tv[j];
        }
    }
    __syncthreads();

    if (tid == 0) {
        g_count[b] = 0u;   // reset for next graph replay

        float mS[6];
        #pragma unroll
        for (int j = 0; j < 6; j++) {
            float s = 0.f;
            #pragma unroll
            for (int wv = 0; wv < 8; wv++) s += warpSums[wv][j];
            mS[j] = s;
        }
        const float inv = 1.0f / (float)NPTS;
        float mp0 = mS[0] * inv, mp1 = mS[1] * inv, mp2 = mS[2] * inv;
        float mq0 = mS[3] * inv, mq1 = mS[4] * inv, mq2 = mS[5] * inv;

        float v0 = sTv[9], v1 = sTv[10], v2 = sTv[11];
        float X[9];
        X[0] = sTv[0] - v0 * mq0; X[1] = sTv[1] - v0 * mq1; X[2] = sTv[2] - v0 * mq2;
        X[3] = sTv[3] - v1 * mq0; X[4] = sTv[4] - v1 * mq1; X[5] = sTv[5] - v1 * mq2;
        X[6] = sTv[6] - v2 * mq0; X[7] = sTv[7] - v2 * mq1; X[8] = sTv[8] - v2 * mq2;

        // Newton polar iteration (det-scaled): X -> 0.5*(g*X + sgn*g^2*cof(X))
        #pragma unroll
        for (int itn = 0; itn < 12; itn++) {
            float C[9];
            C[0] = X[4] * X[8] - X[5] * X[7];
            C[1] = X[5] * X[6] - X[3] * X[8];
            C[2] = X[3] * X[7] - X[4] * X[6];
            C[3] = X[2] * X[7] - X[1] * X[8];
            C[4] = X[0] * X[8] - X[2] * X[6];
            C[5] = X[1] * X[6] - X[0] * X[7];
            C[6] = X[1] * X[5] - X[2] * X[4];
            C[7] = X[2] * X[3] - X[0] * X[5];
            C[8] = X[0] * X[4] - X[1] * X[3];
            float det = X[0] * C[0] + X[1] * C[1] + X[2] * C[2];
            float g = rcbrtf(fabsf(det));
            float g2s = copysignf(g * g, det);
            #pragma unroll
            for (int i = 0; i < 9; i++) X[i] = 0.5f * (g * X[i] + g2s * C[i]);
        }

        float R[9];
        #pragma unroll
        for (int i = 0; i < 3; i++)
            #pragma unroll
            for (int j = 0; j < 3; j++)
                R[i * 3 + j] = X[j * 3 + i];

        float* Rout = out + b * 9;
        float* tout = out + BATCH * 9 + b * 3;
        float mp[3] = {mp0, mp1, mp2};
        float mq[3] = {mq0, mq1, mq2};
        #pragma unroll
        for (int i = 0; i < 3; i++) {
            float ti = mq[i];
            #pragma unroll
            for (int j = 0; j < 3; j++) {
                Rout[i * 3 + j] = R[i * 3 + j];
                ti -= R[i * 3 + j] * mp[j];
            }
            tout[i] = ti;
        }
    }
}

// ---------------------------------------------------------------------------
extern "C" void kernel_launch(void* const* d_in, const int* in_sizes, int n_in,
                              void* d_out, int out_size) {
    const float* P = (const float*)d_in[0];   // Ppc [8,2048,3]
    const float* Q = (const float*)d_in[1];   // Qpc [8,2048,3]
    const float* M = (const float*)d_in[2];   // M   [8,2048,2048]
    float* out = (float*)d_out;               // 72 R + 24 t

    fused_kernel<<<dim3(GRIDX, BATCH), 256>>>(P, Q, M, out);
}